// round 13
// baseline (speedup 1.0000x reference)
#include <cuda_runtime.h>

// out = segment_sum(x, batch); batch sorted int32, N=1e6, C=128, G=10000.
// softmax over size-1 axis == 1.0 -> W/b dead inputs.
// R13: persistent co-resident grid (SMs x 10 blocks, regs/smem sized so the
// entire grid is wave-1 resident -> zero wave transitions). Each block runs
// a producer slice of the offsets scatter (start+1 encoding into g_start1),
// then strides over segments g = bid, bid+grid, ... with the R10 roofline
// streaming loop. Spin waits are per-entry and only bite on the first
// segment; producers are the lowest bids so they can never be starved.

#define C 128
#define C4 (C / 4)
#define WARPS 4
#define TPB (WARPS * 32)
#define MAX_SEG 10000
#define IPT 4                  // int4 elements per producer thread
#define BLOCKS_PER_SM 10

__device__ int g_start1[MAX_SEG + 1];   // start[g]+1 ; 0 means not ready

__device__ __forceinline__ void f4add(float4& a, const float4& v) {
    a.x += v.x; a.y += v.y; a.z += v.z; a.w += v.w;
}

__global__ __launch_bounds__(TPB, BLOCKS_PER_SM) void fused_kernel(
    const float4* __restrict__ x4,
    const int4*  __restrict__ batch4,
    const int*   __restrict__ batch,
    float4* __restrict__ out4,
    int n, int n4, int nwork, int nseg)
{
    const int bid  = blockIdx.x;
    const int warp = threadIdx.x >> 5;
    const int lane = threadIdx.x & 31;       // channels [4*lane, 4*lane+4)

    // -------- producer role (lowest nwork bids) --------
    if (bid < nwork) {
        int base = (bid * TPB + threadIdx.x) * IPT;
        #pragma unroll
        for (int k = 0; k < IPT; ++k) {
            int i = base + k;
            if (i < n4) {
                int4 v = __ldg(&batch4[i]);
                int prev = (i == 0) ? -1 : __ldg(&batch[4 * i - 1]);
                if (v.x != prev) for (int q = prev + 1; q <= v.x; ++q) g_start1[q] = 4 * i + 1;
                if (v.y != v.x)  for (int q = v.x + 1;  q <= v.y; ++q) g_start1[q] = 4 * i + 2;
                if (v.z != v.y)  for (int q = v.y + 1;  q <= v.z; ++q) g_start1[q] = 4 * i + 3;
                if (v.w != v.z)  for (int q = v.z + 1;  q <= v.w; ++q) g_start1[q] = 4 * i + 4;
                if (4 * i + 4 >= n)
                    for (int q = v.w + 1; q <= nseg; ++q) g_start1[q] = n + 1;
            }
        }
        __threadfence();                     // publish to L2 for all consumers
    }

    // -------- consumer role: strided loop over segments --------
    __shared__ int s_se[2];
    __shared__ float4 sacc[WARPS][C4];

    for (int g = bid; g < nseg; g += gridDim.x) {
        if (threadIdx.x == 0) {
            volatile int* vs = g_start1;
            int a = 0, b = 0;
            for (;;) {                       // only non-trivial on 1st segment
                if (a == 0) a = vs[g];
                if (b == 0) b = vs[g + 1];
                if (a != 0 && b != 0) break;
                __nanosleep(32);
            }
            s_se[0] = a - 1;
            s_se[1] = b - 1;
        }
        __syncthreads();
        const int s = s_se[0];
        const int e = s_se[1];

        float4 a0 = make_float4(0.f, 0.f, 0.f, 0.f);
        float4 a1 = make_float4(0.f, 0.f, 0.f, 0.f);
        float4 a2 = make_float4(0.f, 0.f, 0.f, 0.f);
        float4 a3 = make_float4(0.f, 0.f, 0.f, 0.f);

        const float4* p = x4 + (size_t)s * C4 + lane;
        int len = e - s;
        int r = warp;

        for (; r + 3 * WARPS < len; r += 4 * WARPS) {
            float4 v0 = __ldcs(p + (size_t)(r            ) * C4);
            float4 v1 = __ldcs(p + (size_t)(r +     WARPS) * C4);
            float4 v2 = __ldcs(p + (size_t)(r + 2 * WARPS) * C4);
            float4 v3 = __ldcs(p + (size_t)(r + 3 * WARPS) * C4);
            f4add(a0, v0); f4add(a1, v1); f4add(a2, v2); f4add(a3, v3);
        }
        for (; r < len; r += WARPS)
            f4add(a0, __ldcs(p + (size_t)r * C4));

        f4add(a0, a1); f4add(a2, a3); f4add(a0, a2);

        sacc[warp][lane] = a0;
        __syncthreads();

        if (warp == 0) {
            float4 a = sacc[0][lane], b = sacc[1][lane],
                   c = sacc[2][lane], d = sacc[3][lane];
            a.x += b.x + c.x + d.x;
            a.y += b.y + c.y + d.y;
            a.z += b.z + c.z + d.z;
            a.w += b.w + c.w + d.w;
            out4[(size_t)g * C4 + lane] = a; // direct store; zeros if empty
        }
        __syncthreads();                     // sacc/s_se reuse safety
    }
}

extern "C" void kernel_launch(void* const* d_in, const int* in_sizes, int n_in,
                              void* d_out, int out_size)
{
    const float4* x4    = (const float4*)d_in[0];
    const int*    batch = (const int*)d_in[1];
    // d_in[2] = W, d_in[3] = b : dead (softmax over size-1 axis)
    float4* out4 = (float4*)d_out;

    const int n     = in_sizes[0] / C;       // rows of x (1e6, divisible by 4)
    const int nseg  = out_size / C;          // segments (10000)
    const int n4    = n / 4;                 // int4 elements of batch
    const int nwork = (n4 + TPB * IPT - 1) / (TPB * IPT);  // 489 producer blocks

    int sms = 148;
    cudaDeviceGetAttribute(&sms, cudaDevAttrMultiProcessorCount, 0);
    int grid = sms * BLOCKS_PER_SM;          // fully co-resident persistent grid
    if (grid > nseg) grid = nseg;
    if (grid < nwork) grid = nwork;          // all producers must be resident

    fused_kernel<<<grid, TPB>>>(x4, (const int4*)batch, batch, out4,
                                n, n4, nwork, nseg);
}

// round 14
// speedup vs baseline: 1.0288x; 1.0288x over previous
#include <cuda_runtime.h>

// out = segment_sum(x, batch); batch sorted int32, N=1e6, C=128, G=10000.
// softmax over size-1 axis == 1.0 -> W/b dead inputs.
// R14: R12 structure restored (best: grid = nseg, producer role folded into
// the lowest 489 blocks, per-entry spin, roofline streaming loop). R13's
// persistent grid regressed (static striding -> straggler imbalance; the
// oversubscribed grid was acting as a load balancer). Micro-tweak: __stcs
// evict-first output stores to keep L2 clean for the x stream.

#define C 128
#define C4 (C / 4)
#define WARPS 4
#define TPB (WARPS * 32)
#define MAX_SEG 10000
#define IPT 4                  // int4 elements per producer thread

__device__ int g_start1[MAX_SEG + 1];   // start[g]+1 ; 0 means not ready

__device__ __forceinline__ void f4add(float4& a, const float4& v) {
    a.x += v.x; a.y += v.y; a.z += v.z; a.w += v.w;
}

__global__ __launch_bounds__(TPB) void fused_kernel(
    const float4* __restrict__ x4,
    const int4*  __restrict__ batch4,
    const int*   __restrict__ batch,
    float4* __restrict__ out4,
    int n, int n4, int nwork, int nseg)
{
    const int g    = blockIdx.x;             // segment id == block id
    const int warp = threadIdx.x >> 5;
    const int lane = threadIdx.x & 31;       // channels [4*lane, 4*lane+4)

    // -------- producer role (first nwork blocks, then fall through) --------
    if (g < nwork) {
        int base = (g * TPB + threadIdx.x) * IPT;
        #pragma unroll
        for (int k = 0; k < IPT; ++k) {
            int i = base + k;
            if (i < n4) {
                int4 v = __ldg(&batch4[i]);
                int prev = (i == 0) ? -1 : __ldg(&batch[4 * i - 1]);
                if (v.x != prev) for (int q = prev + 1; q <= v.x; ++q) g_start1[q] = 4 * i + 1;
                if (v.y != v.x)  for (int q = v.x + 1;  q <= v.y; ++q) g_start1[q] = 4 * i + 2;
                if (v.z != v.y)  for (int q = v.y + 1;  q <= v.z; ++q) g_start1[q] = 4 * i + 3;
                if (v.w != v.z)  for (int q = v.z + 1;  q <= v.w; ++q) g_start1[q] = 4 * i + 4;
                if (4 * i + 4 >= n)
                    for (int q = v.w + 1; q <= nseg; ++q) g_start1[q] = n + 1;
            }
        }
        __threadfence();                     // publish to L2 for all consumers
    }

    // -------- consumer role: one block per segment --------
    __shared__ int s_se[2];
    if (threadIdx.x == 0) {
        volatile int* vs = g_start1;
        int a = 0, b = 0;
        for (;;) {                           // spin on both entries together
            if (a == 0) a = vs[g];
            if (b == 0) b = vs[g + 1];
            if (a != 0 && b != 0) break;
            __nanosleep(32);
        }
        s_se[0] = a - 1;
        s_se[1] = b - 1;
    }
    __syncthreads();
    const int s = s_se[0];
    const int e = s_se[1];

    float4 a0 = make_float4(0.f, 0.f, 0.f, 0.f);
    float4 a1 = make_float4(0.f, 0.f, 0.f, 0.f);
    float4 a2 = make_float4(0.f, 0.f, 0.f, 0.f);
    float4 a3 = make_float4(0.f, 0.f, 0.f, 0.f);

    const float4* p = x4 + (size_t)s * C4 + lane;
    int len = e - s;
    int r = warp;

    for (; r + 3 * WARPS < len; r += 4 * WARPS) {
        float4 v0 = __ldcs(p + (size_t)(r            ) * C4);
        float4 v1 = __ldcs(p + (size_t)(r +     WARPS) * C4);
        float4 v2 = __ldcs(p + (size_t)(r + 2 * WARPS) * C4);
        float4 v3 = __ldcs(p + (size_t)(r + 3 * WARPS) * C4);
        f4add(a0, v0); f4add(a1, v1); f4add(a2, v2); f4add(a3, v3);
    }
    for (; r < len; r += WARPS)
        f4add(a0, __ldcs(p + (size_t)r * C4));

    f4add(a0, a1); f4add(a2, a3); f4add(a0, a2);

    __shared__ float4 sacc[WARPS][C4];
    sacc[warp][lane] = a0;
    __syncthreads();

    if (warp == 0) {
        float4 a = sacc[0][lane], b = sacc[1][lane],
               c = sacc[2][lane], d = sacc[3][lane];
        a.x += b.x + c.x + d.x;
        a.y += b.y + c.y + d.y;
        a.z += b.z + c.z + d.z;
        a.w += b.w + c.w + d.w;
        __stcs(&out4[(size_t)g * C4 + lane], a);   // evict-first store
    }
}

extern "C" void kernel_launch(void* const* d_in, const int* in_sizes, int n_in,
                              void* d_out, int out_size)
{
    const float4* x4    = (const float4*)d_in[0];
    const int*    batch = (const int*)d_in[1];
    // d_in[2] = W, d_in[3] = b : dead (softmax over size-1 axis)
    float4* out4 = (float4*)d_out;

    const int n     = in_sizes[0] / C;       // rows of x (1e6, divisible by 4)
    const int nseg  = out_size / C;          // segments (10000)
    const int n4    = n / 4;                 // int4 elements of batch
    const int nwork = (n4 + TPB * IPT - 1) / (TPB * IPT);  // 489 producer blocks

    fused_kernel<<<nseg, TPB>>>(x4, (const int4*)batch, batch, out4,
                                n, n4, nwork, nseg);
}